// round 15
// baseline (speedup 1.0000x reference)
#include <cuda_runtime.h>
#include <cuda_fp16.h>
#include <math.h>
#include <stdint.h>

#define DDIM 256
#define NQMAX 40000

// ---------------- scratch (device globals; zero-initialized, no allocation) --
__device__ __align__(16) float g_oa  [NQMAX * 144];    // offsets+logits
__device__ __align__(16) float g_tmp [NQMAX * DDIM];   // fp32 GEMM outputs (pre-LN)
__device__ __align__(16) float g_y   [NQMAX * DDIM];   // ln1 fp32 (residual for ln2)

// fp16 activation streams
__device__ __align__(16) __half g_q16[NQMAX * DDIM];   // query
__device__ __align__(16) __half g_a16[NQMAX * DDIM];   // value input
__device__ __align__(16) __half g_v16[NQMAX * DDIM];   // value projection (msda gathers)
__device__ __align__(16) __half g_m16[NQMAX * DDIM];   // msda out
__device__ __align__(16) __half g_y16[NQMAX * DDIM];   // ln1 out
__device__ __align__(16) __half g_h16[NQMAX * DDIM];   // gelu hidden

// transposed fp16 weights: [N][K=256]   (oa padded to 256 rows, zeros)
__device__ __align__(16) __half g_bv[DDIM * DDIM];
__device__ __align__(16) __half g_bo[DDIM * DDIM];
__device__ __align__(16) __half g_b1[DDIM * DDIM];
__device__ __align__(16) __half g_b2[DDIM * DDIM];
__device__ __align__(16) __half g_boaw[DDIM * DDIM];
__device__ __align__(16) float g_boa[144];

// ---------------- helpers ------------------------------------------------------
__device__ __forceinline__ uint32_t smem_u32(const void* p) {
    uint32_t a;
    asm("{ .reg .u64 t; cvta.to.shared.u64 t, %1; cvt.u32.u64 %0, t; }" : "=r"(a) : "l"(p));
    return a;
}

__device__ __forceinline__ uint32_t pack_h2(__half x, __half y) {
    __half2 t(x, y);
    return *reinterpret_cast<uint32_t*>(&t);
}

__device__ __forceinline__ float gelu_exact(float x) {
    return 0.5f * x * (1.0f + erff(x * 0.70710678118654752f));
}

#define LDSM4(r, addr) \
    asm volatile("ldmatrix.sync.aligned.m8n8.x4.shared.b16 {%0,%1,%2,%3}, [%4];" \
        : "=r"((r)[0]), "=r"((r)[1]), "=r"((r)[2]), "=r"((r)[3]) : "r"(addr))

#define CP_ASYNC16(dst, src) \
    asm volatile("cp.async.ca.shared.global [%0], [%1], 16;" :: "r"(dst), "l"(src))
#define CP_ASYNC16Z(dst, src, sz) \
    asm volatile("cp.async.ca.shared.global [%0], [%1], 16, %2;" \
                 :: "r"(dst), "l"(src), "r"(sz))
#define CP_COMMIT() asm volatile("cp.async.commit_group;" ::: "memory")
#define CP_WAIT(n)  asm volatile("cp.async.wait_group %0;" :: "n"(n) : "memory")

__device__ __forceinline__ void mma_f16(float* d, const uint32_t* a,
                                        uint32_t b0, uint32_t b1) {
    asm volatile(
        "mma.sync.aligned.m16n8k16.row.col.f32.f16.f16.f32 "
        "{%0,%1,%2,%3}, {%4,%5,%6,%7}, {%8,%9}, {%0,%1,%2,%3};"
        : "+f"(d[0]), "+f"(d[1]), "+f"(d[2]), "+f"(d[3])
        : "r"(a[0]), "r"(a[1]), "r"(a[2]), "r"(a[3]), "r"(b0), "r"(b1));
}

// ---------------- HMMA GEMM v9: 4-stage cp.async pipeline, single sync ---------
// C = A[M][256] @ B^T + bias.  CTA tile 128x128, 8 warps (4x2), BK=16.
// MODE 0: fp32 Cf.  MODE 1: gelu -> fp16 Ch.  MODE 2: fp16 Ch (no gelu).
// FULLN=0: clamp warp's nb range via unrolled break (oa GEMM, N=144).
template<int MODE, int FULLN>
__global__ __launch_bounds__(256, 2)
void gemm_mma(const __half* __restrict__ A,
              const __half* __restrict__ B,
              const float* __restrict__ bias,
              float* __restrict__ Cf, __half* __restrict__ Ch,
              int M, int N) {
    extern __shared__ __align__(128) char smem[];
    const uint32_t sb = smem_u32(smem);
    const int tid = threadIdx.x;
    const int wid = tid >> 5;
    const int lane = tid & 31;
    const int m0 = blockIdx.y * 128;
    const int n0 = blockIdx.x * 128;
    const int wr = wid & 3;
    const int wc = wid >> 2;

    constexpr int RB = 48;             // smem row bytes (32 data + 16 pad)
    constexpr int STG = 128 * RB;      // 6144 per array
    constexpr int SSTR = 2 * STG;      // 12288 per stage; 4 stages = 48KB

    int nbLim = 4;
    if (!FULLN) {
        const int rem = N - n0 - wc * 64;
        nbLim = rem >= 64 ? 4 : (rem <= 0 ? 0 : (rem + 15) >> 4);
    }

    float acc[2][8][4];
#pragma unroll
    for (int i = 0; i < 2; ++i)
#pragma unroll
        for (int j = 0; j < 8; ++j)
#pragma unroll
            for (int k = 0; k < 4; ++k) acc[i][j][k] = 0.f;

    const int row = tid >> 1;
    const int half = tid & 1;
    const uint32_t dstOff = row * RB + half * 16;
    const int arow = min(m0 + row, M - 1);
    const uint32_t aValid = (m0 + row < M) ? 16u : 0u;
    const __half* aSrc = A + (size_t)arow * DDIM + half * 8;
    const __half* bSrc = B + (size_t)(n0 + row) * DDIM + half * 8;

#define ISSUE(c) do { \
    const uint32_t base = sb + ((c) & 3) * SSTR + dstOff; \
    CP_ASYNC16Z(base,       aSrc + (c) * 16, aValid); \
    CP_ASYNC16(base + STG,  bSrc + (c) * 16); \
    CP_COMMIT(); } while (0)

    ISSUE(0);
    ISSUE(1);
    ISSUE(2);

    const uint32_t lmA = (wr * 32 + (lane & 15)) * RB + (lane >> 4) * 16;
    const uint32_t lmB = (wc * 64 + (lane & 15)) * RB + (lane >> 4) * 16;

    for (int c = 0; c < 16; ++c) {
        const uint32_t stg = sb + (c & 3) * SSTR;
        if (c <= 13)      CP_WAIT(2);
        else if (c == 14) CP_WAIT(1);
        else              CP_WAIT(0);
        __syncthreads();
        if (c + 3 < 16) ISSUE(c + 3);

        uint32_t ah[2][4];
#pragma unroll
        for (int mr = 0; mr < 2; ++mr)
            LDSM4(ah[mr], stg + lmA + mr * 16 * RB);

#pragma unroll
        for (int nb = 0; nb < 4; ++nb) {
            if (!FULLN && nb >= nbLim) break;
            uint32_t bh[4];
            LDSM4(bh, stg + STG + lmB + nb * 16 * RB);
#pragma unroll
            for (int mr = 0; mr < 2; ++mr) {
                mma_f16(acc[mr][nb * 2 + 0], ah[mr], bh[0], bh[2]);
                mma_f16(acc[mr][nb * 2 + 1], ah[mr], bh[1], bh[3]);
            }
        }
    }

    // ---- epilogue ----
#pragma unroll
    for (int mr = 0; mr < 2; ++mr) {
        const int r0 = m0 + wr * 32 + mr * 16 + (lane >> 2);
#pragma unroll
        for (int f = 0; f < 8; ++f) {
            const int col = n0 + wc * 64 + f * 8 + (lane & 3) * 2;
            if (col >= N) continue;
            const float b0 = bias[col], b1 = bias[col + 1];
#pragma unroll
            for (int h = 0; h < 2; ++h) {
                const int r = r0 + h * 8;
                if (r >= M) continue;
                float x0 = acc[mr][f][h * 2 + 0] + b0;
                float x1 = acc[mr][f][h * 2 + 1] + b1;
                if (MODE == 1) { x0 = gelu_exact(x0); x1 = gelu_exact(x1); }
                if (MODE >= 1) {
                    *reinterpret_cast<uint32_t*>(Ch + (size_t)r * DDIM + col) =
                        pack_h2(__float2half(x0), __float2half(x1));
                } else {
                    *reinterpret_cast<float2*>(Cf + (size_t)r * N + col) = make_float2(x0, x1);
                }
            }
        }
    }
#undef ISSUE
}

// ---------------- fp32 -> fp16 activation convert ------------------------------
__global__ __launch_bounds__(256)
void split_act(const float* __restrict__ x, __half* __restrict__ h, int n4) {
    const int i = blockIdx.x * 256 + threadIdx.x;
    if (i >= n4) return;
    const float4 v = __ldg(reinterpret_cast<const float4*>(x) + i);
    uint2 hv = make_uint2(pack_h2(__float2half(v.x), __float2half(v.y)),
                          pack_h2(__float2half(v.z), __float2half(v.w)));
    *reinterpret_cast<uint2*>(h + (size_t)i * 4) = hv;
}

// ---------------- weight transpose + fp16 convert (once per launch) -----------
__global__ __launch_bounds__(256)
void convert_weights(const float* __restrict__ Wv, const float* __restrict__ Wo,
                     const float* __restrict__ W1, const float* __restrict__ W2,
                     const float* __restrict__ Woff, const float* __restrict__ Wattn,
                     const float* __restrict__ boff, const float* __restrict__ battn) {
    const int b = blockIdx.x;
    const int k = threadIdx.x;
    if (b == 1168) {
        if (k < 96) g_boa[k] = boff[k];
        else if (k < 144) g_boa[k] = battn[k - 96];
        return;
    }
    const float* W; __half* oh; int n, nout, N;
    if (b < 256)       { W = Wv; oh = g_bv; n = b;        nout = n; N = 256; }
    else if (b < 512)  { W = Wo; oh = g_bo; n = b - 256;  nout = n; N = 256; }
    else if (b < 768)  { W = W1; oh = g_b1; n = b - 512;  nout = n; N = 256; }
    else if (b < 1024) { W = W2; oh = g_b2; n = b - 768;  nout = n; N = 256; }
    else {
        nout = b - 1024;  // 0..143
        oh = g_boaw;
        if (nout < 96) { W = Woff;  n = nout;      N = 96; }
        else           { W = Wattn; n = nout - 96; N = 48; }
    }
    oh[(size_t)nout * DDIM + k] = __float2half(W[(size_t)k * N + n]);
}

// ---------------- MSDA sampling v4: fp16 gathers, 2 points/iteration ----------
// One warp per (query, head). gather lane = (psub:1 | corner:2 | cg:2):
//   cg = lane&3 (8 channels, one uint4), corner = (lane>>2)&3, psub = lane>>4.
// Iteration i handles points p = 2i+psub (i=0..2). Metadata lanes as in v3.
__global__ __launch_bounds__(256)
void msda_sample_kernel(const float* __restrict__ oa, const __half* __restrict__ v,
                        const float* __restrict__ ref, const int* __restrict__ ss,
                        __half* __restrict__ out) {
    const int q = blockIdx.x;
    const int h = threadIdx.x >> 5;
    const int lane = threadIdx.x & 31;
    const int cg = lane & 3;            // uint4 group (8 halves)
    const int corner = (lane >> 2) & 3;
    const int psub = lane >> 4;

    const int H = ss[0];
    const int W = ss[1];

    const float bx = __ldg(ref + q * 2 + 0) * (float)W - 0.5f;
    const float by = __ldg(ref + q * 2 + 1) * (float)H - 0.5f;

    const float* qa = oa + (size_t)q * 144;

    // ---- metadata role (unchanged from v3): lane pc<24 owns (p=pc>>2, c=pc&3)
    const int p_m = lane >> 2;
    const int c_m = lane & 3;
    const bool metaValid = (p_m < 6);

    float lg_own = metaValid ? __ldg(qa + 96 + h * 6 + p_m) : -1e30f;
    float mx = lg_own;
#pragma unroll
    for (int o = 4; o <= 16; o <<= 1)
        mx = fmaxf(mx, __shfl_xor_sync(0xffffffffu, mx, o));
    float e = metaValid ? __expf(lg_own - mx) : 0.f;
    float sum = e;
#pragma unroll
    for (int o = 4; o <= 16; o <<= 1)
        sum += __shfl_xor_sync(0xffffffffu, sum, o);
    const float a_own = e / sum;

    const int pp = metaValid ? p_m : 0;
    const float ox = __ldg(qa + h * 12 + pp * 2 + 0);
    const float oy = __ldg(qa + h * 12 + pp * 2 + 1);
    const float lx = bx + ox;
    const float ly = by + oy;
    const float x0f = floorf(lx);
    const float y0f = floorf(ly);
    const float fx = lx - x0f;
    const float fy = ly - y0f;
    const int dxm = c_m & 1;
    const int dym = c_m >> 1;
    const int xi = (int)x0f + dxm;
    const int yi = (int)y0f + dym;
    const float wx = dxm ? fx : 1.f - fx;
    const float wy = dym ? fy : 1.f - fy;
    const bool valid = metaValid & (xi >= 0) & (xi < W) & (yi >= 0) & (yi < H);
    const float wv = valid ? a_own * wx * wy : 0.f;
    const uint32_t xc = (uint32_t)min(max(xi, 0), W - 1);
    const uint32_t yc = (uint32_t)min(max(yi, 0), H - 1);
    const uint32_t off_own = (yc * (uint32_t)W + xc) * 32u;   // uint4 units (256 halves/row)

    // ---- gather role ----
    const uint4* vh = reinterpret_cast<const uint4*>(v) + (h * 4 + cg);
    float acc[8];
#pragma unroll
    for (int j = 0; j < 8; ++j) acc[j] = 0.f;

#pragma unroll
    for (int i = 0; i < 3; ++i) {
        const int p = 2 * i + psub;
        const int src = p * 4 + corner;
        const uint32_t off = __shfl_sync(0xffffffffu, off_own, src);
        const float w = __shfl_sync(0xffffffffu, wv, src);
        const uint4 raw = __ldg(vh + off);
        const __half2* hp = reinterpret_cast<const __half2*>(&raw);
#pragma unroll
        for (int j = 0; j < 4; ++j) {
            const float2 f = __half22float2(hp[j]);
            acc[2 * j + 0] += w * f.x;
            acc[2 * j + 1] += w * f.y;
        }
    }

    // reduce over corner (xor 4, 8) and psub (xor 16)
#pragma unroll
    for (int o = 4; o <= 16; o <<= 1) {
#pragma unroll
        for (int j = 0; j < 8; ++j)
            acc[j] += __shfl_xor_sync(0xffffffffu, acc[j], o);
    }
    if (lane < 4) {
        uint4 hv;
        hv.x = pack_h2(__float2half(acc[0]), __float2half(acc[1]));
        hv.y = pack_h2(__float2half(acc[2]), __float2half(acc[3]));
        hv.z = pack_h2(__float2half(acc[4]), __float2half(acc[5]));
        hv.w = pack_h2(__float2half(acc[6]), __float2half(acc[7]));
        *reinterpret_cast<uint4*>(out + (size_t)q * DDIM + h * 32 + cg * 8) = hv;
    }
}

// ---------------- fused residual + LayerNorm: one warp per row -----------------
template<int SPLIT>
__global__ __launch_bounds__(256)
void ln_kernel(const float* __restrict__ x, const float* __restrict__ res,
               const float* __restrict__ g, const float* __restrict__ b,
               float* __restrict__ out, __half* __restrict__ out16, int M) {
    const int row = blockIdx.x * 8 + (threadIdx.x >> 5);
    if (row >= M) return;
    const int lane = threadIdx.x & 31;
    const size_t base = (size_t)row * DDIM + lane * 8;

    float4 v0 = *reinterpret_cast<const float4*>(x + base);
    float4 v1 = *reinterpret_cast<const float4*>(x + base + 4);
    const float4 r0 = *reinterpret_cast<const float4*>(res + base);
    const float4 r1 = *reinterpret_cast<const float4*>(res + base + 4);
    v0.x += r0.x; v0.y += r0.y; v0.z += r0.z; v0.w += r0.w;
    v1.x += r1.x; v1.y += r1.y; v1.z += r1.z; v1.w += r1.w;

    float s  = v0.x + v0.y + v0.z + v0.w + v1.x + v1.y + v1.z + v1.w;
    float s2 = v0.x * v0.x + v0.y * v0.y + v0.z * v0.z + v0.w * v0.w
             + v1.x * v1.x + v1.y * v1.y + v1.z * v1.z + v1.w * v1.w;
#pragma unroll
    for (int o = 16; o; o >>= 1) {
        s  += __shfl_xor_sync(0xffffffffu, s, o);
        s2 += __shfl_xor_sync(0xffffffffu, s2, o);
    }
    const float mean = s * (1.f / 256.f);
    const float var  = s2 * (1.f / 256.f) - mean * mean;
    const float rstd = rsqrtf(var + 1e-5f);

    const float4 g0 = *reinterpret_cast<const float4*>(g + lane * 8);
    const float4 g1 = *reinterpret_cast<const float4*>(g + lane * 8 + 4);
    const float4 b0 = *reinterpret_cast<const float4*>(b + lane * 8);
    const float4 b1 = *reinterpret_cast<const float4*>(b + lane * 8 + 4);

    float4 o0, o1;
    o0.x = (v0.x - mean) * rstd * g0.x + b0.x;
    o0.y = (v0.y - mean) * rstd * g0.y + b0.y;
    o0.z = (v0.z - mean) * rstd * g0.z + b0.z;
    o0.w = (v0.w - mean) * rstd * g0.w + b0.w;
    o1.x = (v1.x - mean) * rstd * g1.x + b1.x;
    o1.y = (v1.y - mean) * rstd * g1.y + b1.y;
    o1.z = (v1.z - mean) * rstd * g1.z + b1.z;
    o1.w = (v1.w - mean) * rstd * g1.w + b1.w;
    *reinterpret_cast<float4*>(out + base)     = o0;
    *reinterpret_cast<float4*>(out + base + 4) = o1;
    if (SPLIT) {
        uint4 hv;
        hv.x = pack_h2(__float2half(o0.x), __float2half(o0.y));
        hv.y = pack_h2(__float2half(o0.z), __float2half(o0.w));
        hv.z = pack_h2(__float2half(o1.x), __float2half(o1.y));
        hv.w = pack_h2(__float2half(o1.z), __float2half(o1.w));
        *reinterpret_cast<uint4*>(out16 + base) = hv;
    }
}

// ---------------- launch --------------------------------------------------------
extern "C" void kernel_launch(void* const* d_in, const int* in_sizes, int n_in,
                              void* d_out, int out_size) {
    const float* query  = (const float*)d_in[0];
    const float* value  = (const float*)d_in[1];
    const float* refp   = (const float*)d_in[2];
    const int*   ss     = (const int*)d_in[3];
    const float* W_off  = (const float*)d_in[5];
    const float* b_off  = (const float*)d_in[6];
    const float* W_attn = (const float*)d_in[7];
    const float* b_attn = (const float*)d_in[8];
    const float* W_val  = (const float*)d_in[9];
    const float* b_val  = (const float*)d_in[10];
    const float* W_out  = (const float*)d_in[11];
    const float* b_out  = (const float*)d_in[12];
    const float* ln1_g  = (const float*)d_in[13];
    const float* ln1_b  = (const float*)d_in[14];
    const float* W1     = (const float*)d_in[15];
    const float* b1     = (const float*)d_in[16];
    const float* W2     = (const float*)d_in[17];
    const float* b2     = (const float*)d_in[18];
    const float* ln2_g  = (const float*)d_in[19];
    const float* ln2_b  = (const float*)d_in[20];
    float* out = (float*)d_out;

    const int M  = in_sizes[0] / DDIM;
    const int Mv = in_sizes[1] / DDIM;

    float *poa, *ptmp, *py, *pboa;
    __half *q16, *a16, *v16, *m16, *y16, *h16;
    __half *bv, *bo, *b1w, *b2w, *boaw;
    cudaGetSymbolAddress((void**)&poa,   g_oa);
    cudaGetSymbolAddress((void**)&ptmp,  g_tmp);
    cudaGetSymbolAddress((void**)&py,    g_y);
    cudaGetSymbolAddress((void**)&pboa,  g_boa);
    cudaGetSymbolAddress((void**)&q16,   g_q16);
    cudaGetSymbolAddress((void**)&a16,   g_a16);
    cudaGetSymbolAddress((void**)&v16,   g_v16);
    cudaGetSymbolAddress((void**)&m16,   g_m16);
    cudaGetSymbolAddress((void**)&y16,   g_y16);
    cudaGetSymbolAddress((void**)&h16,   g_h16);
    cudaGetSymbolAddress((void**)&bv,    g_bv);
    cudaGetSymbolAddress((void**)&bo,    g_bo);
    cudaGetSymbolAddress((void**)&b1w,   g_b1);
    cudaGetSymbolAddress((void**)&b2w,   g_b2);
    cudaGetSymbolAddress((void**)&boaw,  g_boaw);

    const int SMEM = 8 * 128 * 48;  // 49152 bytes (4 stages x 12KB)
    cudaFuncSetAttribute((gemm_mma<0, 1>), cudaFuncAttributeMaxDynamicSharedMemorySize, SMEM);
    cudaFuncSetAttribute((gemm_mma<1, 1>), cudaFuncAttributeMaxDynamicSharedMemorySize, SMEM);
    cudaFuncSetAttribute((gemm_mma<2, 1>), cudaFuncAttributeMaxDynamicSharedMemorySize, SMEM);
    cudaFuncSetAttribute((gemm_mma<0, 0>), cudaFuncAttributeMaxDynamicSharedMemorySize, SMEM);

    const int gM  = (M + 127) / 128;
    const int gMv = (Mv + 127) / 128;
    const int gLN = (M + 7) / 8;

    // 0) weights -> transposed fp16; activations -> fp16
    convert_weights<<<1169, 256>>>(W_val, W_out, W1, W2, W_off, W_attn, b_off, b_attn);
    split_act<<<(M * 64 + 255) / 256, 256>>>(query, q16, M * 64);
    split_act<<<(Mv * 64 + 255) / 256, 256>>>(value, a16, Mv * 64);
    // 1) value projection -> fp16
    gemm_mma<2, 1><<<dim3(2, gMv), 256, SMEM>>>(a16, bv, b_val, nullptr, v16, Mv, DDIM);
    // 2) fused offsets+attn logits GEMM (N=144, statically clamped)
    gemm_mma<0, 0><<<dim3(2, gM), 256, SMEM>>>(q16, boaw, pboa, poa, nullptr, M, 144);
    // 3) deformable sampling (fp16 gathers) -> fp16
    msda_sample_kernel<<<M, 256>>>(poa, v16, refp, ss, m16);
    // 4) output projection + residual + LN1
    gemm_mma<0, 1><<<dim3(2, gM), 256, SMEM>>>(m16, bo, b_out, ptmp, nullptr, M, DDIM);
    ln_kernel<1><<<gLN, 256>>>(ptmp, query, ln1_g, ln1_b, py, y16, M);
    // 5) FFN
    gemm_mma<1, 1><<<dim3(2, gM), 256, SMEM>>>(y16, b1w, b1, nullptr, h16, M, DDIM);
    gemm_mma<0, 1><<<dim3(2, gM), 256, SMEM>>>(h16, b2w, b2, ptmp, nullptr, M, DDIM);
    ln_kernel<0><<<gLN, 256>>>(ptmp, py, ln2_g, ln2_b, out, nullptr, M);
}